// round 13
// baseline (speedup 1.0000x reference)
#include <cuda_runtime.h>
#include <cuda_fp16.h>
#include <math.h>
#include <stdint.h>

#define BATCH   4096
#define SEQ     64
#define CDIM    256
#define HEADS   8
#define HDIM    32
#define NW      64
#define MROWS   (BATCH * SEQ)        // 262144
#define QKVDIM  768
#define GK      256
#define LOG2E   1.4426950408889634f
#define MAXLOG  4.6051701859880914f

// Scratch. q/k/v stored HEAD-MAJOR: section s in {q=0..7, k=8..15, v=16..23},
// addr = (s * MROWS + row) * HDIM + d.  (v uses only _hi.)
__device__ __half g_qkv_hi[(size_t)24 * MROWS * HDIM];
__device__ __half g_qkv_mid[(size_t)16 * MROWS * HDIM];  // q/k only
__device__ __half g_x_hi[(size_t)MROWS * CDIM];
__device__ __half g_x_mid[(size_t)MROWS * CDIM];
__device__ __half g_att[(size_t)MROWS * CDIM];        // attention out (fp16)
__device__ __half g_wq_hi[QKVDIM * GK];
__device__ __half g_wq_mid[QKVDIM * GK];
__device__ __half g_wp_hi[CDIM * GK];                 // proj W single fp16
__device__ float g_rope_cos[SEQ * 16];
__device__ float g_rope_sin[SEQ * 16];
__device__ float g_mask2[NW * SEQ * SEQ];   // mask * log2(e)

#define SW128(b) ((b) ^ (((b) >> 3) & 0x70))

__device__ __forceinline__ uint32_t smem_u32(const void* p) {
    uint32_t a;
    asm("{ .reg .u64 t; cvta.to.shared.u64 t, %1; cvt.u32.u64 %0, t; }"
        : "=r"(a) : "l"(p));
    return a;
}
__device__ __forceinline__ void ldmatrix_x4(uint32_t* r, uint32_t addr) {
    asm volatile("ldmatrix.sync.aligned.m8n8.x4.shared.b16 {%0,%1,%2,%3}, [%4];"
                 : "=r"(r[0]), "=r"(r[1]), "=r"(r[2]), "=r"(r[3]) : "r"(addr));
}
__device__ __forceinline__ void mma_f32acc(float* c, const uint32_t* a,
                                           const uint32_t* b) {
    asm volatile(
        "mma.sync.aligned.m16n8k16.row.col.f32.f16.f16.f32 "
        "{%0,%1,%2,%3}, {%4,%5,%6,%7}, {%8,%9}, {%0,%1,%2,%3};"
        : "+f"(c[0]), "+f"(c[1]), "+f"(c[2]), "+f"(c[3])
        : "r"(a[0]), "r"(a[1]), "r"(a[2]), "r"(a[3]), "r"(b[0]), "r"(b[1]));
}
__device__ __forceinline__ void mma_f16acc(uint32_t* c, const uint32_t* a,
                                           const uint32_t* b) {
    asm volatile(
        "mma.sync.aligned.m16n8k16.row.col.f16.f16.f16.f16 "
        "{%0,%1}, {%2,%3,%4,%5}, {%6,%7}, {%0,%1};"
        : "+r"(c[0]), "+r"(c[1])
        : "r"(a[0]), "r"(a[1]), "r"(a[2]), "r"(a[3]), "r"(b[0]), "r"(b[1]));
}
__device__ __forceinline__ void cp16(uint32_t dst, const void* src) {
    asm volatile("cp.async.cg.shared.global [%0], [%1], 16;"
                 :: "r"(dst), "l"(src));
}
#define CP_COMMIT() asm volatile("cp.async.commit_group;" ::: "memory")
#define CP_WAIT(n)  asm volatile("cp.async.wait_group %0;" :: "n"(n) : "memory")

__device__ __forceinline__ uint32_t h2ex2(uint32_t v) {
    asm("ex2.approx.f16x2 %0, %0;" : "+r"(v));
    return v;
}
__device__ __forceinline__ void split2h(float a, float b,
                                        uint32_t& hi, uint32_t& mid) {
    __half ha = __float2half_rn(a);
    __half hb = __float2half_rn(b);
    __half2 hp = __halves2half2(ha, hb);
    hi = *(uint32_t*)&hp;
    __half2 mp = __floats2half2_rn(a - __half2float(ha), b - __half2float(hb));
    mid = *(uint32_t*)&mp;
}
__device__ __forceinline__ uint32_t pack_h2(float a, float b) {
    __half2 hp = __floats2half2_rn(a, b);
    return *(uint32_t*)&hp;
}
__device__ __forceinline__ float2 unpack_h2(uint32_t v) {
    return __half22float2(*(__half2*)&v);
}

// ===========================================================================
// Merged init kernel: block-range dispatch
// ===========================================================================
#define NB_X    65536
#define NB_M    256
#define NB_WQ   192
#define NB_WP   64
#define NB_ROPE 4
#define NB_TOTAL (NB_X + NB_M + NB_WQ + NB_WP + NB_ROPE)

__global__ void __launch_bounds__(256)
init_kernel(const float* __restrict__ x,
            const float* __restrict__ mask,
            const float* __restrict__ qkv_w,
            const float* __restrict__ proj_w)
{
    int b = blockIdx.x;
    int tid = threadIdx.x;
    if (b < NB_X) {
        size_t i = (size_t)b * 256 + tid;
        float4 v = *(const float4*)&x[i * 4];
        uint32_t h0, m0, h1, m1;
        split2h(v.x, v.y, h0, m0);
        split2h(v.z, v.w, h1, m1);
        *(uint2*)&g_x_hi[i * 4]  = make_uint2(h0, h1);
        *(uint2*)&g_x_mid[i * 4] = make_uint2(m0, m1);
        return;
    }
    b -= NB_X;
    if (b < NB_M) {
        size_t i = (size_t)b * 256 + tid;
        float4 v = *(const float4*)&mask[i * 4];
        v.x *= LOG2E; v.y *= LOG2E; v.z *= LOG2E; v.w *= LOG2E;
        *(float4*)&g_mask2[i * 4] = v;
        return;
    }
    b -= NB_M;
    if (b < NB_WQ) {
        size_t i = (size_t)b * 256 + tid;
        float4 v = *(const float4*)&qkv_w[i * 4];
        uint32_t h0, m0, h1, m1;
        split2h(v.x, v.y, h0, m0);
        split2h(v.z, v.w, h1, m1);
        *(uint2*)&g_wq_hi[i * 4]  = make_uint2(h0, h1);
        *(uint2*)&g_wq_mid[i * 4] = make_uint2(m0, m1);
        return;
    }
    b -= NB_WQ;
    if (b < NB_WP) {
        size_t i = (size_t)b * 256 + tid;
        float4 v = *(const float4*)&proj_w[i * 4];
        *(uint2*)&g_wp_hi[i * 4] =
            make_uint2(pack_h2(v.x, v.y), pack_h2(v.z, v.w));
        return;
    }
    b -= NB_WP;
    {
        int i = b * 256 + tid;      // 0..1023
        int n = i >> 4;
        int f = i & 15;
        const float NEG_LN1E4_OVER16 = -0.57564627324851142f;
        float inv = expf((float)f * NEG_LN1E4_OVER16);
        float t = (float)n + 0.1f;
        float s, c;
        sincosf(t * inv, &s, &c);
        g_rope_cos[i] = c;
        g_rope_sin[i] = s;
    }
}

// ===========================================================================
// QKV GEMM: q/k cols 3-term; v cols 1-term. Head-major coalesced output.
// ===========================================================================
#define KC       64
#define S_AHI    0
#define S_AMID   16384
#define S_BHI    32768
#define S_BMID   40960
#define STAGE_BYTES 49152
#define SMEM_GEMM_BYTES (2 * STAGE_BYTES)   // 98304

__device__ __forceinline__ void qkv_prefetch(
    uint32_t sb, int stage,
    const __half* Ahi, const __half* Amid,
    const __half* Whi, const __half* Wmid,
    int k0, int tid, bool t3)
{
    uint32_t base = sb + stage * STAGE_BYTES;
#pragma unroll
    for (int i = 0; i < 4; i++) {
        int idx = i * 256 + tid;
        int r   = idx >> 3;
        int c16 = idx & 7;
        uint32_t d = SW128((uint32_t)(r * 128 + c16 * 16));
        cp16(base + S_AHI + d, Ahi + (size_t)r * GK + k0 + c16 * 8);
        if (t3)
            cp16(base + S_AMID + d, Amid + (size_t)r * GK + k0 + c16 * 8);
    }
#pragma unroll
    for (int i = 0; i < 2; i++) {
        int idx = i * 256 + tid;
        int r   = idx >> 3;
        int c16 = idx & 7;
        uint32_t d = SW128((uint32_t)(r * 128 + c16 * 16));
        cp16(base + S_BHI + d, Whi + (size_t)r * GK + k0 + c16 * 8);
        if (t3)
            cp16(base + S_BMID + d, Wmid + (size_t)r * GK + k0 + c16 * 8);
    }
}

__global__ void __launch_bounds__(256, 2)
gemm_qkv_kernel(const __half* __restrict__ Ahi,
                const __half* __restrict__ Amid,
                const __half* __restrict__ Whi,
                const __half* __restrict__ Wmid,
                const float* __restrict__ bias,
                __half* __restrict__ Ohi,
                __half* __restrict__ Omid,
                const float* __restrict__ ls)
{
    extern __shared__ char smem[];
    const uint32_t sb = smem_u32(smem);
    const int tid  = threadIdx.x;
    const int wid  = tid >> 5;
    const int lane = tid & 31;
    const int wm   = wid & 3;
    const int wn   = wid >> 2;
    const int row0 = blockIdx.y * 128;
    const int col0 = blockIdx.x * 64;
    const bool t3  = col0 < 512;          // q/k columns

    const __half* Ah = Ahi  + (size_t)row0 * GK;
    const __half* Am = Amid + (size_t)row0 * GK;
    const __half* Wh = Whi  + (size_t)col0 * GK;
    const __half* Wm = Wmid + (size_t)col0 * GK;

    float acc[2][4][4];
    uint32_t hacc[2][4][2];
#pragma unroll
    for (int mt = 0; mt < 2; mt++)
#pragma unroll
        for (int nt = 0; nt < 4; nt++) {
#pragma unroll
            for (int e = 0; e < 4; e++) acc[mt][nt][e] = 0.f;
            hacc[mt][nt][0] = 0u; hacc[mt][nt][1] = 0u;
        }

    const int arow  = wm * 32 + (lane & 15);
    const int acol8 = (lane >> 4) * 8;
    const int bn_lo = wn * 32 + ((lane >> 4) << 3) + (lane & 7);
    const int bc8   = ((lane >> 3) & 1) << 3;

    qkv_prefetch(sb, 0, Ah, Am, Wh, Wm, 0, tid, t3);
    CP_COMMIT();

    const int NC = GK / KC;   // 4
#pragma unroll
    for (int c = 0; c < NC; c++) {
        if (c + 1 < NC) {
            qkv_prefetch(sb, (c + 1) & 1, Ah, Am, Wh, Wm, (c + 1) * KC, tid, t3);
            CP_COMMIT();
            CP_WAIT(1);
        } else {
            CP_WAIT(0);
        }
        __syncthreads();

        uint32_t base = sb + (c & 1) * STAGE_BYTES;
#pragma unroll
        for (int ks = 0; ks < 4; ks++) {
            uint32_t ah[2][4], am[2][4], bh[2][4], bm[2][4];
            const int kcA = ks * 16 + acol8;
#pragma unroll
            for (int mt = 0; mt < 2; mt++) {
                uint32_t off = SW128((uint32_t)((arow + mt * 16) * 128 + kcA * 2));
                ldmatrix_x4(ah[mt], base + S_AHI + off);
                if (t3)
                    ldmatrix_x4(am[mt], base + S_AMID + off);
            }
            const int kcB = ks * 16 + bc8;
#pragma unroll
            for (int pp = 0; pp < 2; pp++) {
                uint32_t off = SW128((uint32_t)((bn_lo + pp * 16) * 128 + kcB * 2));
                ldmatrix_x4(bh[pp], base + S_BHI + off);
            }
            if (t3) {
#pragma unroll
                for (int pp = 0; pp < 2; pp++) {
                    uint32_t off = SW128((uint32_t)((bn_lo + pp * 16) * 128 + kcB * 2));
                    ldmatrix_x4(bm[pp], base + S_BMID + off);
                }
            }
#pragma unroll
            for (int mt = 0; mt < 2; mt++)
#pragma unroll
                for (int nt = 0; nt < 4; nt++) {
                    const uint32_t* bhp = &bh[nt >> 1][(nt & 1) * 2];
                    mma_f32acc(acc[mt][nt], ah[mt], bhp);
                    if (t3) {
                        const uint32_t* bmp = &bm[nt >> 1][(nt & 1) * 2];
                        mma_f16acc(hacc[mt][nt], ah[mt], bmp);
                        mma_f16acc(hacc[mt][nt], am[mt], bhp);
                    }
                }
        }
        __syncthreads();
    }

    const int coff = (lane & 3) * 2;

    float* scos = (float*)smem;
    float* ssin = scos + SEQ * 16;
    if (t3) {
        for (int i = tid; i < SEQ * 16; i += 256) {
            scos[i] = g_rope_cos[i];
            ssin[i] = g_rope_sin[i];
        }
        __syncthreads();
    }

    const int hcol = col0 + wn * 32;          // head-aligned base column
    const int sec  = hcol >> 5;               // section index 0..23
    __half* Oh = Ohi  + (size_t)sec * MROWS * HDIM;
    __half* Om = Omid + (size_t)sec * MROWS * HDIM;

    float qscale = 1.f;
    if (t3 && hcol < 256)
        qscale = __expf(fminf(ls[(hcol >> 5) & 7], MAXLOG)) * LOG2E;

#pragma unroll
    for (int mt = 0; mt < 2; mt++) {
        int rA = row0 + wm * 32 + mt * 16 + (lane >> 2);
        float vA[4][2], vB[4][2];
#pragma unroll
        for (int nt = 0; nt < 4; nt++) {
            int c_ = hcol + nt * 8 + coff;
            float2 bv = *(const float2*)&bias[c_];
            float2 cl = unpack_h2(hacc[mt][nt][0]);
            float2 ch = unpack_h2(hacc[mt][nt][1]);
            vA[nt][0] = acc[mt][nt][0] + cl.x + bv.x;
            vA[nt][1] = acc[mt][nt][1] + cl.y + bv.y;
            vB[nt][0] = acc[mt][nt][2] + ch.x + bv.x;
            vB[nt][1] = acc[mt][nt][3] + ch.y + bv.y;
        }
        if (t3) {
            const int nA = rA & 63;
            const int nB = nA + 8;
            float yA[4][2], yB[4][2];
#pragma unroll
            for (int ntL = 0; ntL < 2; ntL++)
#pragma unroll
                for (int e = 0; e < 2; e++) {
                    int f = ntL * 8 + coff + e;
                    float cA = scos[nA * 16 + f], sA = ssin[nA * 16 + f];
                    float cB = scos[nB * 16 + f], sB = ssin[nB * 16 + f];
                    float x1 = vA[ntL][e], x2 = vA[ntL + 2][e];
                    yA[ntL][e]     = x1 * cA - x2 * sA;
                    yA[ntL + 2][e] = x1 * sA + x2 * cA;
                    x1 = vB[ntL][e]; x2 = vB[ntL + 2][e];
                    yB[ntL][e]     = x1 * cB - x2 * sB;
                    yB[ntL + 2][e] = x1 * sB + x2 * cB;
                }
            float ssA = 0.f, ssB = 0.f;
#pragma unroll
            for (int nt = 0; nt < 4; nt++)
#pragma unroll
                for (int e = 0; e < 2; e++) {
                    ssA += yA[nt][e] * yA[nt][e];
                    ssB += yB[nt][e] * yB[nt][e];
                }
            ssA += __shfl_xor_sync(0xffffffffu, ssA, 1);
            ssA += __shfl_xor_sync(0xffffffffu, ssA, 2);
            ssB += __shfl_xor_sync(0xffffffffu, ssB, 1);
            ssB += __shfl_xor_sync(0xffffffffu, ssB, 2);
            float iA = rsqrtf(fmaxf(ssA, 1e-24f)) * qscale;
            float iB = rsqrtf(fmaxf(ssB, 1e-24f)) * qscale;
#pragma unroll
            for (int nt = 0; nt < 4; nt++) {
                int d = nt * 8 + coff;
                uint32_t h0, m0, h1, m1;
                split2h(yA[nt][0] * iA, yA[nt][1] * iA, h0, m0);
                split2h(yB[nt][0] * iB, yB[nt][1] * iB, h1, m1);
                size_t a0 = (size_t)rA * HDIM + d;
                size_t a1 = (size_t)(rA + 8) * HDIM + d;
                *(uint32_t*)&Oh[a0] = h0;
                *(uint32_t*)&Om[a0] = m0;
                *(uint32_t*)&Oh[a1] = h1;
                *(uint32_t*)&Om[a1] = m1;
            }
        } else {
#pragma unroll
            for (int nt = 0; nt < 4; nt++) {
                int d = nt * 8 + coff;
                size_t a0 = (size_t)rA * HDIM + d;
                size_t a1 = (size_t)(rA + 8) * HDIM + d;
                *(uint32_t*)&Oh[a0] = pack_h2(vA[nt][0], vA[nt][1]);
                *(uint32_t*)&Oh[a1] = pack_h2(vB[nt][0], vB[nt][1]);
            }
        }
    }
}

// ===========================================================================
// Proj GEMM: pure fp16 operands, f32 accum.
// ===========================================================================
#define PS_A     0
#define PS_B     16384
#define PSTAGE   24576
#define SMEM_PROJ_BYTES (2 * PSTAGE)   // 49152

__device__ __forceinline__ void proj_prefetch(
    uint32_t sb, int stage,
    const __half* A, const __half* W, int k0, int tid)
{
    uint32_t base = sb + stage * PSTAGE;
#pragma unroll
    for (int i = 0; i < 4; i++) {
        int idx = i * 256 + tid;
        int r   = idx >> 3;
        int c16 = idx & 7;
        uint32_t d = SW128((uint32_t)(r * 128 + c16 * 16));
        cp16(base + PS_A + d, A + (size_t)r * GK + k0 + c16 * 8);
    }
#pragma unroll
    for (int i = 0; i < 2; i++) {
        int idx = i * 256 + tid;
        int r   = idx >> 3;
        int c16 = idx & 7;
        uint32_t d = SW128((uint32_t)(r * 128 + c16 * 16));
        cp16(base + PS_B + d, W + (size_t)r * GK + k0 + c16 * 8);
    }
}

__global__ void __launch_bounds__(256, 2)
gemm_proj_kernel(const __half* __restrict__ A,
                 const __half* __restrict__ W,
                 const float* __restrict__ bias,
                 float* __restrict__ C)
{
    extern __shared__ char smem[];
    const uint32_t sb = smem_u32(smem);
    const int tid  = threadIdx.x;
    const int wid  = tid >> 5;
    const int lane = tid & 31;
    const int wm   = wid & 3;
    const int wn   = wid >> 2;
    const int row0 = blockIdx.y * 128;
    const int col0 = blockIdx.x * 64;

    const __half* Ab = A + (size_t)row0 * GK;
    const __half* Wb = W + (size_t)col0 * GK;

    float acc[2][4][4];
#pragma unroll
    for (int mt = 0; mt < 2; mt++)
#pragma unroll
        for (int nt = 0; nt < 4; nt++)
#pragma unroll
            for (int e = 0; e < 4; e++) acc[mt][nt][e] = 0.f;

    const int arow  = wm * 32 + (lane & 15);
    const int acol8 = (lane >> 4) * 8;
    const int bn_lo = wn * 32 + ((lane >> 4) << 3) + (lane & 7);
    const int bc8   = ((lane >> 3) & 1) << 3;

    proj_prefetch(sb, 0, Ab, Wb, 0, tid);
    CP_COMMIT();

    const int NC = GK / KC;   // 4
#pragma unroll
    for (int c = 0; c < NC; c++) {
        if (c + 1 < NC) {
            proj_prefetch(sb, (c + 1) & 1, Ab, Wb, (c + 1) * KC, tid);
            CP_COMMIT();
            CP_WAIT(1);
        } else {
            CP_WAIT(0);
        }
        __syncthreads();

        uint32_t base = sb + (c & 1) * PSTAGE;
#pragma unroll
        for (int ks = 0; ks < 4; ks++) {
            uint32_t ah[2][4], bh[2][4];
            const int kcA = ks * 16 + acol8;
#pragma unroll
            for (int mt = 0; mt < 2; mt++) {
                uint32_t off = SW128((uint32_t)((arow + mt * 16) * 128 + kcA * 2));
                ldmatrix_x4(ah[mt], base + PS_A + off);
            }
            const int kcB = ks * 16 + bc8;
#pragma unroll
            for (int pp = 0; pp < 2; pp++) {
                uint32_t off = SW128((uint32_t)((bn_lo + pp * 16) * 128 + kcB * 2));
                ldmatrix_x4(bh[pp], base + PS_B + off);
            }
#pragma unroll
            for (int mt = 0; mt < 2; mt++)
#pragma unroll
                for (int nt = 0; nt < 4; nt++)
                    mma_f32acc(acc[mt][nt], ah[mt], &bh[nt >> 1][(nt & 1) * 2]);
        }
        __syncthreads();
    }

    const int coff = (lane & 3) * 2;
#pragma unroll
    for (int mt = 0; mt < 2; mt++) {
        int r_ = row0 + wm * 32 + mt * 16 + (lane >> 2);
#pragma unroll
        for (int nt = 0; nt < 4; nt++) {
            int c_ = col0 + wn * 32 + nt * 8 + coff;
            float2 bv = *(const float2*)&bias[c_];
            float2 o0, o1;
            o0.x = acc[mt][nt][0] + bv.x;
            o0.y = acc[mt][nt][1] + bv.y;
            o1.x = acc[mt][nt][2] + bv.x;
            o1.y = acc[mt][nt][3] + bv.y;
            *(float2*)&C[(size_t)r_ * CDIM + c_]       = o0;
            *(float2*)&C[(size_t)(r_ + 8) * CDIM + c_] = o1;
        }
    }
}

// ===========================================================================
// Attention: 2 heads per CTA, 256 threads. Head-major contiguous input.
// ===========================================================================
#define QK_STRIDE 80
#define VT_STRIDE 144
#define HB        25088            // per-head smem block
#define O_QHI     0
#define O_QMID    5120
#define O_KHI     10240
#define O_KMID    15360
#define O_VT      20480
#define SMEM_ATTN (2 * HB)         // 50176

__global__ void __launch_bounds__(256)
attn_mma_kernel()
{
    extern __shared__ __align__(16) uint8_t asmem[];

    const int b    = blockIdx.x;
    const int tid  = threadIdx.x;
    const int hg   = tid >> 7;               // head group 0/1
    const int lt   = tid & 127;
    const int lane = tid & 31;
    const int warp = (tid >> 5) & 3;         // warp within head group
    const int h    = blockIdx.y * 2 + hg;
    uint8_t* hb = asmem + hg * HB;

    // ---- phase 1: cp.async contiguous head-major tiles; transpose v ----
    {
        const size_t tilebase = (size_t)(b * SEQ) * HDIM;   // within a section
        const __half* srcs[4] = {
            g_qkv_hi  + ((size_t)h * MROWS) * HDIM + tilebase,          // q hi
            g_qkv_mid + ((size_t)h * MROWS) * HDIM + tilebase,          // q mid
            g_qkv_hi  + ((size_t)(8 + h) * MROWS) * HDIM + tilebase,    // k hi
            g_qkv_mid + ((size_t)(8 + h) * MROWS) * HDIM + tilebase     // k mid
        };
        const int dofs[4] = { O_QHI, O_QMID, O_KHI, O_KMID };
#pragma unroll
        for (int t = 0; t < 4; t++) {
            const __half* src = srcs[t];
            uint32_t dst = smem_u32(hb + dofs[t]);
#pragma unroll
            for (int i = 0; i < 2; i++) {
                int idx = i * 128 + lt;     // 0..255
                int r = idx >> 2, c = idx & 3;
                cp16(dst + r * QK_STRIDE + c * 16, src + r * HDIM + c * 8);
            }
        }
        CP_COMMIT();

        // v: contiguous rows of 64B
        const int j  = lt >> 1;
        const int db = (lt & 1) * 16;
        const __half* vh = g_qkv_hi + ((size_t)(16 + h) * MROWS) * HDIM
                         + tilebase + (size_t)j * HDIM + db;
        uint4 hv0 = *(const uint4*)vh;
        uint4 hv1 = *(const uint4*)(vh + 8);
        uint16_t hs[16];
        *(uint4*)&hs[0] = hv0; *(uint4*)&hs[8] = hv1;
#pragma unroll
        for (int i = 0; i < 16; i++) {
            int d = db + i;
            *(uint16_t*)(hb + O_VT + d * VT_STRIDE + j * 2) = hs[i];
        }
        CP_WAIT(0);
    }
    __syncthreads();

    // ---- mask prefetch (pre-scaled by log2e) ----
    const float* mrow = g_mask2 + (size_t)(b & (NW - 1)) * SEQ * SEQ;
    const int m0   = warp * 16;
    const int r0   = m0 + (lane >> 2);
    const int r1   = r0 + 8;
    const int coff = (lane & 3) * 2;
    float2 mA[8], mB[8];
#pragma unroll
    for (int nt = 0; nt < 8; nt++) {
        mA[nt] = *(const float2*)&mrow[r0 * SEQ + nt * 8 + coff];
        mB[nt] = *(const float2*)&mrow[r1 * SEQ + nt * 8 + coff];
    }

    // ---- QK^T ----
    const int ar  = lane & 15;
    const int ac8 = (lane >> 4) * 8;
    const int bnp = ((lane >> 4) << 3) + (lane & 7);
    const int bc8 = ((lane >> 3) & 1) << 3;

    uint32_t ah[2][4], am[2][4];
#pragma unroll
    for (int kt = 0; kt < 2; kt++) {
        uint32_t off = (uint32_t)((m0 + ar) * QK_STRIDE + (kt * 16 + ac8) * 2);
        ldmatrix_x4(ah[kt], smem_u32(hb + O_QHI)  + off);
        ldmatrix_x4(am[kt], smem_u32(hb + O_QMID) + off);
    }

    float acc[8][4];
    uint32_t hqk[8][2];
#pragma unroll
    for (int nt = 0; nt < 8; nt++) {
#pragma unroll
        for (int e = 0; e < 4; e++) acc[nt][e] = 0.f;
        hqk[nt][0] = 0u; hqk[nt][1] = 0u;
    }

#pragma unroll
    for (int pp = 0; pp < 4; pp++) {
        uint32_t bh[2][4], bm[2][4];
#pragma unroll
        for (int kt = 0; kt < 2; kt++) {
            uint32_t off = (uint32_t)((pp * 16 + bnp) * QK_STRIDE
                                      + (kt * 16 + bc8) * 2);
            ldmatrix_x4(bh[kt], smem_u32(hb + O_KHI)  + off);
            ldmatrix_x4(bm[kt], smem_u32(hb + O_KMID) + off);
        }
#pragma unroll
        for (int kt = 0; kt < 2; kt++)
#pragma unroll
            for (int n2 = 0; n2 < 2; n2++) {
                int nt = pp * 2 + n2;
                mma_f32acc(acc[nt], ah[kt], &bh[kt][n2 * 2]);
                mma_f16acc(hqk[nt], ah[kt], &bm[kt][n2 * 2]);
                mma_f16acc(hqk[nt], am[kt], &bh[kt][n2 * 2]);
            }
    }

    // ---- softmax in log2 domain, exp in f16x2 ----
    float mx0 = -1e30f, mx1 = -1e30f;
#pragma unroll
    for (int nt = 0; nt < 8; nt++) {
        float2 cl = unpack_h2(hqk[nt][0]);
        float2 ch = unpack_h2(hqk[nt][1]);
        acc[nt][0] += cl.x + mA[nt].x;
        acc[nt][1] += cl.y + mA[nt].y;
        acc[nt][2] += ch.x + mB[nt].x;
        acc[nt][3] += ch.y + mB[nt].y;
        mx0 = fmaxf(mx0, fmaxf(acc[nt][0], acc[nt][1]));
        mx1 = fmaxf(mx1, fmaxf(acc[nt][2], acc[nt][3]));
    }
    mx0 = fmaxf(mx0, __shfl_xor_sync(0xffffffffu, mx0, 1));
    mx0 = fmaxf(mx0, __shfl_xor_sync(0xffffffffu, mx0, 2));
    mx1 = fmaxf(mx1, __shfl_xor_sync(0xffffffffu, mx1, 1));
    mx1 = fmaxf(mx1, __shfl_xor_sync(0xffffffffu, mx1, 2));

    uint32_t hp[8][2];
    float sum0 = 0.f, sum1 = 0.f;
#pragma unroll
    for (int nt = 0; nt < 8; nt++) {
        uint32_t p0 = h2ex2(pack_h2(acc[nt][0] - mx0, acc[nt][1] - mx0));
        uint32_t p1 = h2ex2(pack_h2(acc[nt][2] - mx1, acc[nt][3] - mx1));
        hp[nt][0] = p0;
        hp[nt][1] = p1;
        float2 f0 = unpack_h2(p0);
        float2 f1 = unpack_h2(p1);
        sum0 += f0.x + f0.y;
        sum1 += f1.x + f1.y;
    }
    sum0 += __shfl_xor_sync(0xffffffffu, sum0, 1);
    sum0 += __shfl_xor_sync(0xffffffffu, sum0, 2);
    sum1 += __shfl_xor_sync(0xffffffffu, sum1, 1);
    sum1 += __shfl_xor_sync(0xffffffffu, sum1, 2);

    // ---- PV (v single fp16) ----
    float oacc[4][4];
#pragma unroll
    for (int dt = 0; dt < 4; dt++)
#pragma unroll
        for (int e = 0; e < 4; e++) oacc[dt][e] = 0.f;

#pragma unroll
    for (int kt = 0; kt < 4; kt++) {
        uint32_t phf[4];
        phf[0] = hp[2 * kt][0];
        phf[1] = hp[2 * kt][1];
        phf[2] = hp[2 * kt + 1][0];
        phf[3] = hp[2 * kt + 1][1];

        uint32_t vh[2][4];
#pragma unroll
        for (int d2 = 0; d2 < 2; d2++) {
            uint32_t off = (uint32_t)((d2 * 16 + bnp) * VT_STRIDE
                                      + (kt * 16 + bc8) * 2);
            ldmatrix_x4(vh[d2], smem_u32(hb + O_VT) + off);
        }
#pragma unroll
        for (int dt = 0; dt < 4; dt++)
            mma_f32acc(oacc[dt], phf, &vh[dt >> 1][(dt & 1) * 2]);
    }

    // ---- epilogue: single fp16 out (row-major for proj) ----
    const float inv0 = 1.f / sum0;
    const float inv1 = 1.f / sum1;
#pragma unroll
    for (int dt = 0; dt < 4; dt++) {
        int col = dt * 8 + coff;
        size_t a0 = ((size_t)(b * SEQ + r0)) * CDIM + h * HDIM + col;
        size_t a1 = ((size_t)(b * SEQ + r1)) * CDIM + h * HDIM + col;
        *(uint32_t*)&g_att[a0] = pack_h2(oacc[dt][0] * inv0, oacc[dt][1] * inv0);
        *(uint32_t*)&g_att[a1] = pack_h2(oacc[dt][2] * inv1, oacc[dt][3] * inv1);
    }
}

// ---------------------------------------------------------------------------
extern "C" void kernel_launch(void* const* d_in, const int* in_sizes, int n_in,
                              void* d_out, int out_size)
{
    const float* x           = (const float*)d_in[0];
    const float* mask        = (const float*)d_in[1];
    const float* qkv_w       = (const float*)d_in[2];
    const float* qkv_b       = (const float*)d_in[3];
    const float* proj_w      = (const float*)d_in[4];
    const float* proj_b      = (const float*)d_in[5];
    const float* logit_scale = (const float*)d_in[6];
    float* out = (float*)d_out;

    __half *qkvh, *qkvm, *xh, *xm, *att, *wqh, *wqm, *wph;
    cudaGetSymbolAddress((void**)&qkvh, g_qkv_hi);
    cudaGetSymbolAddress((void**)&qkvm, g_qkv_mid);
    cudaGetSymbolAddress((void**)&xh,  g_x_hi);
    cudaGetSymbolAddress((void**)&xm,  g_x_mid);
    cudaGetSymbolAddress((void**)&att, g_att);
    cudaGetSymbolAddress((void**)&wqh, g_wq_hi);
    cudaGetSymbolAddress((void**)&wqm, g_wq_mid);
    cudaGetSymbolAddress((void**)&wph, g_wp_hi);

    cudaFuncSetAttribute(gemm_qkv_kernel,
                         cudaFuncAttributeMaxDynamicSharedMemorySize,
                         SMEM_GEMM_BYTES);
    cudaFuncSetAttribute(gemm_proj_kernel,
                         cudaFuncAttributeMaxDynamicSharedMemorySize,
                         SMEM_PROJ_BYTES);
    cudaFuncSetAttribute(attn_mma_kernel,
                         cudaFuncAttributeMaxDynamicSharedMemorySize,
                         SMEM_ATTN);

    // 0) merged init
    init_kernel<<<NB_TOTAL, 256>>>(x, mask, qkv_w, proj_w);

    // 1) QKV GEMM with fused RoPE/norm/split epilogue (head-major out)
    {
        dim3 grid(QKVDIM / 64, MROWS / 128);
        gemm_qkv_kernel<<<grid, 256, SMEM_GEMM_BYTES>>>(
            xh, xm, wqh, wqm, qkv_b, qkvh, qkvm, logit_scale);
    }
    // 2) Attention (2 heads per CTA)
    {
        dim3 grid(BATCH, HEADS / 2);
        attn_mma_kernel<<<grid, 256, SMEM_ATTN>>>();
    }
    // 3) Proj GEMM (pure fp16 operands, f32 accum)
    {
        dim3 grid(CDIM / 64, MROWS / 128);
        gemm_proj_kernel<<<grid, 256, SMEM_PROJ_BYTES>>>(att, wph, proj_b, out);
    }
}

// round 14
// speedup vs baseline: 1.4009x; 1.4009x over previous
#include <cuda_runtime.h>
#include <cuda_fp16.h>
#include <math.h>
#include <stdint.h>

#define BATCH   4096
#define SEQ     64
#define CDIM    256
#define HEADS   8
#define HDIM    32
#define NW      64
#define MROWS   (BATCH * SEQ)        // 262144
#define QKVDIM  768
#define GK      256
#define LOG2E   1.4426950408889634f
#define MAXLOG  4.6051701859880914f

// Scratch (device globals) — R11 row-major layout
__device__ __half g_qkv_hi[(size_t)MROWS * QKVDIM];   // q|k hi, v (single)
__device__ __half g_qkv_mid[(size_t)MROWS * QKVDIM];  // q|k mid (v unused)
__device__ __half g_x_hi[(size_t)MROWS * CDIM];
__device__ __half g_x_mid[(size_t)MROWS * CDIM];
__device__ __half g_att[(size_t)MROWS * CDIM];        // attention out (fp16)
__device__ __half g_wq_hi[QKVDIM * GK];
__device__ __half g_wq_mid[QKVDIM * GK];
__device__ __half g_wp_hi[CDIM * GK];                 // proj W single fp16
__device__ float g_rope_cos[SEQ * 16];
__device__ float g_rope_sin[SEQ * 16];
__device__ float g_mask2[NW * SEQ * SEQ];   // mask * log2(e)

#define SW128(b) ((b) ^ (((b) >> 3) & 0x70))

__device__ __forceinline__ uint32_t smem_u32(const void* p) {
    uint32_t a;
    asm("{ .reg .u64 t; cvta.to.shared.u64 t, %1; cvt.u32.u64 %0, t; }"
        : "=r"(a) : "l"(p));
    return a;
}
__device__ __forceinline__ void ldmatrix_x4(uint32_t* r, uint32_t addr) {
    asm volatile("ldmatrix.sync.aligned.m8n8.x4.shared.b16 {%0,%1,%2,%3}, [%4];"
                 : "=r"(r[0]), "=r"(r[1]), "=r"(r[2]), "=r"(r[3]) : "r"(addr));
}
__device__ __forceinline__ void mma_f32acc(float* c, const uint32_t* a,
                                           const uint32_t* b) {
    asm volatile(
        "mma.sync.aligned.m16n8k16.row.col.f32.f16.f16.f32 "
        "{%0,%1,%2,%3}, {%4,%5,%6,%7}, {%8,%9}, {%0,%1,%2,%3};"
        : "+f"(c[0]), "+f"(c[1]), "+f"(c[2]), "+f"(c[3])
        : "r"(a[0]), "r"(a[1]), "r"(a[2]), "r"(a[3]), "r"(b[0]), "r"(b[1]));
}
__device__ __forceinline__ void mma_f16acc(uint32_t* c, const uint32_t* a,
                                           const uint32_t* b) {
    asm volatile(
        "mma.sync.aligned.m16n8k16.row.col.f16.f16.f16.f16 "
        "{%0,%1}, {%2,%3,%4,%5}, {%6,%7}, {%0,%1};"
        : "+r"(c[0]), "+r"(c[1])
        : "r"(a[0]), "r"(a[1]), "r"(a[2]), "r"(a[3]), "r"(b[0]), "r"(b[1]));
}
__device__ __forceinline__ void cp16(uint32_t dst, const void* src) {
    asm volatile("cp.async.cg.shared.global [%0], [%1], 16;"
                 :: "r"(dst), "l"(src));
}
#define CP_COMMIT() asm volatile("cp.async.commit_group;" ::: "memory")
#define CP_WAIT(n)  asm volatile("cp.async.wait_group %0;" :: "n"(n) : "memory")

__device__ __forceinline__ uint32_t h2ex2(uint32_t v) {
    asm("ex2.approx.f16x2 %0, %0;" : "+r"(v));
    return v;
}
__device__ __forceinline__ void split2h(float a, float b,
                                        uint32_t& hi, uint32_t& mid) {
    __half ha = __float2half_rn(a);
    __half hb = __float2half_rn(b);
    __half2 hp = __halves2half2(ha, hb);
    hi = *(uint32_t*)&hp;
    __half2 mp = __floats2half2_rn(a - __half2float(ha), b - __half2float(hb));
    mid = *(uint32_t*)&mp;
}
__device__ __forceinline__ uint32_t pack_h2(float a, float b) {
    __half2 hp = __floats2half2_rn(a, b);
    return *(uint32_t*)&hp;
}
__device__ __forceinline__ float2 unpack_h2(uint32_t v) {
    return __half22float2(*(__half2*)&v);
}

// ===========================================================================
// Merged init kernel: block-range dispatch
// ===========================================================================
#define NB_X    65536
#define NB_M    256
#define NB_WQ   192
#define NB_WP   64
#define NB_ROPE 4
#define NB_TOTAL (NB_X + NB_M + NB_WQ + NB_WP + NB_ROPE)

__global__ void __launch_bounds__(256)
init_kernel(const float* __restrict__ x,
            const float* __restrict__ mask,
            const float* __restrict__ qkv_w,
            const float* __restrict__ proj_w)
{
    int b = blockIdx.x;
    int tid = threadIdx.x;
    if (b < NB_X) {
        size_t i = (size_t)b * 256 + tid;
        float4 v = *(const float4*)&x[i * 4];
        uint32_t h0, m0, h1, m1;
        split2h(v.x, v.y, h0, m0);
        split2h(v.z, v.w, h1, m1);
        *(uint2*)&g_x_hi[i * 4]  = make_uint2(h0, h1);
        *(uint2*)&g_x_mid[i * 4] = make_uint2(m0, m1);
        return;
    }
    b -= NB_X;
    if (b < NB_M) {
        size_t i = (size_t)b * 256 + tid;
        float4 v = *(const float4*)&mask[i * 4];
        v.x *= LOG2E; v.y *= LOG2E; v.z *= LOG2E; v.w *= LOG2E;
        *(float4*)&g_mask2[i * 4] = v;
        return;
    }
    b -= NB_M;
    if (b < NB_WQ) {
        size_t i = (size_t)b * 256 + tid;
        float4 v = *(const float4*)&qkv_w[i * 4];
        uint32_t h0, m0, h1, m1;
        split2h(v.x, v.y, h0, m0);
        split2h(v.z, v.w, h1, m1);
        *(uint2*)&g_wq_hi[i * 4]  = make_uint2(h0, h1);
        *(uint2*)&g_wq_mid[i * 4] = make_uint2(m0, m1);
        return;
    }
    b -= NB_WQ;
    if (b < NB_WP) {
        size_t i = (size_t)b * 256 + tid;
        float4 v = *(const float4*)&proj_w[i * 4];
        *(uint2*)&g_wp_hi[i * 4] =
            make_uint2(pack_h2(v.x, v.y), pack_h2(v.z, v.w));
        return;
    }
    b -= NB_WP;
    {
        int i = b * 256 + tid;      // 0..1023
        int n = i >> 4;
        int f = i & 15;
        const float NEG_LN1E4_OVER16 = -0.57564627324851142f;
        float inv = expf((float)f * NEG_LN1E4_OVER16);
        float t = (float)n + 0.1f;
        float s, c;
        sincosf(t * inv, &s, &c);
        g_rope_cos[i] = c;
        g_rope_sin[i] = s;
    }
}

// ===========================================================================
// QKV GEMM: q/k cols 3-term; v cols 1-term. Row-major output (R11).
// ===========================================================================
#define KC       64
#define S_AHI    0
#define S_AMID   16384
#define S_BHI    32768
#define S_BMID   40960
#define STAGE_BYTES 49152
#define SMEM_GEMM_BYTES (2 * STAGE_BYTES)   // 98304

__device__ __forceinline__ void qkv_prefetch(
    uint32_t sb, int stage,
    const __half* Ahi, const __half* Amid,
    const __half* Whi, const __half* Wmid,
    int k0, int tid, bool t3)
{
    uint32_t base = sb + stage * STAGE_BYTES;
#pragma unroll
    for (int i = 0; i < 4; i++) {
        int idx = i * 256 + tid;
        int r   = idx >> 3;
        int c16 = idx & 7;
        uint32_t d = SW128((uint32_t)(r * 128 + c16 * 16));
        cp16(base + S_AHI + d, Ahi + (size_t)r * GK + k0 + c16 * 8);
        if (t3)
            cp16(base + S_AMID + d, Amid + (size_t)r * GK + k0 + c16 * 8);
    }
#pragma unroll
    for (int i = 0; i < 2; i++) {
        int idx = i * 256 + tid;
        int r   = idx >> 3;
        int c16 = idx & 7;
        uint32_t d = SW128((uint32_t)(r * 128 + c16 * 16));
        cp16(base + S_BHI + d, Whi + (size_t)r * GK + k0 + c16 * 8);
        if (t3)
            cp16(base + S_BMID + d, Wmid + (size_t)r * GK + k0 + c16 * 8);
    }
}

__global__ void __launch_bounds__(256, 2)
gemm_qkv_kernel(const __half* __restrict__ Ahi,
                const __half* __restrict__ Amid,
                const __half* __restrict__ Whi,
                const __half* __restrict__ Wmid,
                const float* __restrict__ bias,
                __half* __restrict__ Ohi,
                __half* __restrict__ Omid,
                const float* __restrict__ ls)
{
    extern __shared__ char smem[];
    const uint32_t sb = smem_u32(smem);
    const int tid  = threadIdx.x;
    const int wid  = tid >> 5;
    const int lane = tid & 31;
    const int wm   = wid & 3;
    const int wn   = wid >> 2;
    const int row0 = blockIdx.y * 128;
    const int col0 = blockIdx.x * 64;
    const bool t3  = col0 < 512;          // q/k columns

    const __half* Ah = Ahi  + (size_t)row0 * GK;
    const __half* Am = Amid + (size_t)row0 * GK;
    const __half* Wh = Whi  + (size_t)col0 * GK;
    const __half* Wm = Wmid + (size_t)col0 * GK;

    float acc[2][4][4];
    uint32_t hacc[2][4][2];
#pragma unroll
    for (int mt = 0; mt < 2; mt++)
#pragma unroll
        for (int nt = 0; nt < 4; nt++) {
#pragma unroll
            for (int e = 0; e < 4; e++) acc[mt][nt][e] = 0.f;
            hacc[mt][nt][0] = 0u; hacc[mt][nt][1] = 0u;
        }

    const int arow  = wm * 32 + (lane & 15);
    const int acol8 = (lane >> 4) * 8;
    const int bn_lo = wn * 32 + ((lane >> 4) << 3) + (lane & 7);
    const int bc8   = ((lane >> 3) & 1) << 3;

    qkv_prefetch(sb, 0, Ah, Am, Wh, Wm, 0, tid, t3);
    CP_COMMIT();

    const int NC = GK / KC;   // 4
#pragma unroll
    for (int c = 0; c < NC; c++) {
        if (c + 1 < NC) {
            qkv_prefetch(sb, (c + 1) & 1, Ah, Am, Wh, Wm, (c + 1) * KC, tid, t3);
            CP_COMMIT();
            CP_WAIT(1);
        } else {
            CP_WAIT(0);
        }
        __syncthreads();

        uint32_t base = sb + (c & 1) * STAGE_BYTES;
#pragma unroll
        for (int ks = 0; ks < 4; ks++) {
            uint32_t ah[2][4], am[2][4], bh[2][4], bm[2][4];
            const int kcA = ks * 16 + acol8;
#pragma unroll
            for (int mt = 0; mt < 2; mt++) {
                uint32_t off = SW128((uint32_t)((arow + mt * 16) * 128 + kcA * 2));
                ldmatrix_x4(ah[mt], base + S_AHI + off);
                if (t3)
                    ldmatrix_x4(am[mt], base + S_AMID + off);
            }
            const int kcB = ks * 16 + bc8;
#pragma unroll
            for (int pp = 0; pp < 2; pp++) {
                uint32_t off = SW128((uint32_t)((bn_lo + pp * 16) * 128 + kcB * 2));
                ldmatrix_x4(bh[pp], base + S_BHI + off);
            }
            if (t3) {
#pragma unroll
                for (int pp = 0; pp < 2; pp++) {
                    uint32_t off = SW128((uint32_t)((bn_lo + pp * 16) * 128 + kcB * 2));
                    ldmatrix_x4(bm[pp], base + S_BMID + off);
                }
            }
#pragma unroll
            for (int mt = 0; mt < 2; mt++)
#pragma unroll
                for (int nt = 0; nt < 4; nt++) {
                    const uint32_t* bhp = &bh[nt >> 1][(nt & 1) * 2];
                    mma_f32acc(acc[mt][nt], ah[mt], bhp);
                    if (t3) {
                        const uint32_t* bmp = &bm[nt >> 1][(nt & 1) * 2];
                        mma_f16acc(hacc[mt][nt], ah[mt], bmp);
                        mma_f16acc(hacc[mt][nt], am[mt], bhp);
                    }
                }
        }
        __syncthreads();
    }

    const int coff = (lane & 3) * 2;

    float* scos = (float*)smem;
    float* ssin = scos + SEQ * 16;
    if (t3) {
        for (int i = tid; i < SEQ * 16; i += 256) {
            scos[i] = g_rope_cos[i];
            ssin[i] = g_rope_sin[i];
        }
        __syncthreads();
    }

    const int hcol = col0 + wn * 32;
    float qscale = 1.f;
    if (t3 && hcol < 256)
        qscale = __expf(fminf(ls[(hcol >> 5) & 7], MAXLOG)) * LOG2E;

#pragma unroll
    for (int mt = 0; mt < 2; mt++) {
        int rA = row0 + wm * 32 + mt * 16 + (lane >> 2);
        float vA[4][2], vB[4][2];
#pragma unroll
        for (int nt = 0; nt < 4; nt++) {
            int c_ = hcol + nt * 8 + coff;
            float2 bv = *(const float2*)&bias[c_];
            float2 cl = unpack_h2(hacc[mt][nt][0]);
            float2 ch = unpack_h2(hacc[mt][nt][1]);
            vA[nt][0] = acc[mt][nt][0] + cl.x + bv.x;
            vA[nt][1] = acc[mt][nt][1] + cl.y + bv.y;
            vB[nt][0] = acc[mt][nt][2] + ch.x + bv.x;
            vB[nt][1] = acc[mt][nt][3] + ch.y + bv.y;
        }
        if (t3) {
            const int nA = rA & 63;
            const int nB = nA + 8;
            float yA[4][2], yB[4][2];
#pragma unroll
            for (int ntL = 0; ntL < 2; ntL++)
#pragma unroll
                for (int e = 0; e < 2; e++) {
                    int f = ntL * 8 + coff + e;
                    float cA = scos[nA * 16 + f], sA = ssin[nA * 16 + f];
                    float cB = scos[nB * 16 + f], sB = ssin[nB * 16 + f];
                    float x1 = vA[ntL][e], x2 = vA[ntL + 2][e];
                    yA[ntL][e]     = x1 * cA - x2 * sA;
                    yA[ntL + 2][e] = x1 * sA + x2 * cA;
                    x1 = vB[ntL][e]; x2 = vB[ntL + 2][e];
                    yB[ntL][e]     = x1 * cB - x2 * sB;
                    yB[ntL + 2][e] = x1 * sB + x2 * cB;
                }
            float ssA = 0.f, ssB = 0.f;
#pragma unroll
            for (int nt = 0; nt < 4; nt++)
#pragma unroll
                for (int e = 0; e < 2; e++) {
                    ssA += yA[nt][e] * yA[nt][e];
                    ssB += yB[nt][e] * yB[nt][e];
                }
            ssA += __shfl_xor_sync(0xffffffffu, ssA, 1);
            ssA += __shfl_xor_sync(0xffffffffu, ssA, 2);
            ssB += __shfl_xor_sync(0xffffffffu, ssB, 1);
            ssB += __shfl_xor_sync(0xffffffffu, ssB, 2);
            float iA = rsqrtf(fmaxf(ssA, 1e-24f)) * qscale;
            float iB = rsqrtf(fmaxf(ssB, 1e-24f)) * qscale;
#pragma unroll
            for (int nt = 0; nt < 4; nt++) {
                int c_ = hcol + nt * 8 + coff;
                uint32_t h0, m0, h1, m1;
                split2h(yA[nt][0] * iA, yA[nt][1] * iA, h0, m0);
                split2h(yB[nt][0] * iB, yB[nt][1] * iB, h1, m1);
                size_t a0 = (size_t)rA * QKVDIM + c_;
                size_t a1 = (size_t)(rA + 8) * QKVDIM + c_;
                *(uint32_t*)&Ohi[a0]  = h0;
                *(uint32_t*)&Omid[a0] = m0;
                *(uint32_t*)&Ohi[a1]  = h1;
                *(uint32_t*)&Omid[a1] = m1;
            }
        } else {
#pragma unroll
            for (int nt = 0; nt < 4; nt++) {
                int c_ = hcol + nt * 8 + coff;
                size_t a0 = (size_t)rA * QKVDIM + c_;
                size_t a1 = (size_t)(rA + 8) * QKVDIM + c_;
                *(uint32_t*)&Ohi[a0] = pack_h2(vA[nt][0], vA[nt][1]);
                *(uint32_t*)&Ohi[a1] = pack_h2(vB[nt][0], vB[nt][1]);
            }
        }
    }
}

// ===========================================================================
// Proj GEMM: pure fp16 operands, f32 accum.
// ===========================================================================
#define PS_A     0
#define PS_B     16384
#define PSTAGE   24576
#define SMEM_PROJ_BYTES (2 * PSTAGE)   // 49152

__device__ __forceinline__ void proj_prefetch(
    uint32_t sb, int stage,
    const __half* A, const __half* W, int k0, int tid)
{
    uint32_t base = sb + stage * PSTAGE;
#pragma unroll
    for (int i = 0; i < 4; i++) {
        int idx = i * 256 + tid;
        int r   = idx >> 3;
        int c16 = idx & 7;
        uint32_t d = SW128((uint32_t)(r * 128 + c16 * 16));
        cp16(base + PS_A + d, A + (size_t)r * GK + k0 + c16 * 8);
    }
#pragma unroll
    for (int i = 0; i < 2; i++) {
        int idx = i * 256 + tid;
        int r   = idx >> 3;
        int c16 = idx & 7;
        uint32_t d = SW128((uint32_t)(r * 128 + c16 * 16));
        cp16(base + PS_B + d, W + (size_t)r * GK + k0 + c16 * 8);
    }
}

__global__ void __launch_bounds__(256, 2)
gemm_proj_kernel(const __half* __restrict__ A,
                 const __half* __restrict__ W,
                 const float* __restrict__ bias,
                 float* __restrict__ C)
{
    extern __shared__ char smem[];
    const uint32_t sb = smem_u32(smem);
    const int tid  = threadIdx.x;
    const int wid  = tid >> 5;
    const int lane = tid & 31;
    const int wm   = wid & 3;
    const int wn   = wid >> 2;
    const int row0 = blockIdx.y * 128;
    const int col0 = blockIdx.x * 64;

    const __half* Ab = A + (size_t)row0 * GK;
    const __half* Wb = W + (size_t)col0 * GK;

    float acc[2][4][4];
#pragma unroll
    for (int mt = 0; mt < 2; mt++)
#pragma unroll
        for (int nt = 0; nt < 4; nt++)
#pragma unroll
            for (int e = 0; e < 4; e++) acc[mt][nt][e] = 0.f;

    const int arow  = wm * 32 + (lane & 15);
    const int acol8 = (lane >> 4) * 8;
    const int bn_lo = wn * 32 + ((lane >> 4) << 3) + (lane & 7);
    const int bc8   = ((lane >> 3) & 1) << 3;

    proj_prefetch(sb, 0, Ab, Wb, 0, tid);
    CP_COMMIT();

    const int NC = GK / KC;   // 4
#pragma unroll
    for (int c = 0; c < NC; c++) {
        if (c + 1 < NC) {
            proj_prefetch(sb, (c + 1) & 1, Ab, Wb, (c + 1) * KC, tid);
            CP_COMMIT();
            CP_WAIT(1);
        } else {
            CP_WAIT(0);
        }
        __syncthreads();

        uint32_t base = sb + (c & 1) * PSTAGE;
#pragma unroll
        for (int ks = 0; ks < 4; ks++) {
            uint32_t ah[2][4], bh[2][4];
            const int kcA = ks * 16 + acol8;
#pragma unroll
            for (int mt = 0; mt < 2; mt++) {
                uint32_t off = SW128((uint32_t)((arow + mt * 16) * 128 + kcA * 2));
                ldmatrix_x4(ah[mt], base + PS_A + off);
            }
            const int kcB = ks * 16 + bc8;
#pragma unroll
            for (int pp = 0; pp < 2; pp++) {
                uint32_t off = SW128((uint32_t)((bn_lo + pp * 16) * 128 + kcB * 2));
                ldmatrix_x4(bh[pp], base + PS_B + off);
            }
#pragma unroll
            for (int mt = 0; mt < 2; mt++)
#pragma unroll
                for (int nt = 0; nt < 4; nt++)
                    mma_f32acc(acc[mt][nt], ah[mt], &bh[nt >> 1][(nt & 1) * 2]);
        }
        __syncthreads();
    }

    const int coff = (lane & 3) * 2;
#pragma unroll
    for (int mt = 0; mt < 2; mt++) {
        int r_ = row0 + wm * 32 + mt * 16 + (lane >> 2);
#pragma unroll
        for (int nt = 0; nt < 4; nt++) {
            int c_ = col0 + wn * 32 + nt * 8 + coff;
            float2 bv = *(const float2*)&bias[c_];
            float2 o0, o1;
            o0.x = acc[mt][nt][0] + bv.x;
            o0.y = acc[mt][nt][1] + bv.y;
            o1.x = acc[mt][nt][2] + bv.x;
            o1.y = acc[mt][nt][3] + bv.y;
            *(float2*)&C[(size_t)r_ * CDIM + c_]       = o0;
            *(float2*)&C[(size_t)(r_ + 8) * CDIM + c_] = o1;
        }
    }
}

// ===========================================================================
// Attention: 2 heads per CTA, 256 threads. Row-major input (R11).
// ===========================================================================
#define QK_STRIDE 80
#define VT_STRIDE 144
#define HB        25088            // per-head smem block
#define O_QHI     0
#define O_QMID    5120
#define O_KHI     10240
#define O_KMID    15360
#define O_VT      20480
#define SMEM_ATTN (2 * HB)         // 50176

__global__ void __launch_bounds__(256)
attn_mma_kernel()
{
    extern __shared__ __align__(16) uint8_t asmem[];

    const int b    = blockIdx.x;
    const int tid  = threadIdx.x;
    const int hg   = tid >> 7;               // head group 0/1
    const int lt   = tid & 127;
    const int lane = tid & 31;
    const int warp = (tid >> 5) & 3;         // warp within head group
    const int h    = blockIdx.y * 2 + hg;
    uint8_t* hb = asmem + hg * HB;

    // ---- phase 1: cp.async q/k tiles; transpose v ----
    {
        const size_t rowbase = (size_t)(b * SEQ) * QKVDIM;
        const __half* srcs[4] = {
            g_qkv_hi  + rowbase + h * HDIM,
            g_qkv_mid + rowbase + h * HDIM,
            g_qkv_hi  + rowbase + 256 + h * HDIM,
            g_qkv_mid + rowbase + 256 + h * HDIM
        };
        const int dofs[4] = { O_QHI, O_QMID, O_KHI, O_KMID };
#pragma unroll
        for (int t = 0; t < 4; t++) {
            const __half* src = srcs[t];
            uint32_t dst = smem_u32(hb + dofs[t]);
#pragma unroll
            for (int i = 0; i < 2; i++) {
                int idx = i * 128 + lt;     // 0..255
                int r = idx >> 2, c = idx & 3;
                cp16(dst + r * QK_STRIDE + c * 16,
                     src + (size_t)r * QKVDIM + c * 8);
            }
        }
        CP_COMMIT();

        const int j  = lt >> 1;
        const int db = (lt & 1) * 16;
        const __half* vh = g_qkv_hi + rowbase + (size_t)j * QKVDIM
                         + 512 + h * HDIM + db;
        uint4 hv0 = *(const uint4*)vh;
        uint4 hv1 = *(const uint4*)(vh + 8);
        uint16_t hs[16];
        *(uint4*)&hs[0] = hv0; *(uint4*)&hs[8] = hv1;
#pragma unroll
        for (int i = 0; i < 16; i++) {
            int d = db + i;
            *(uint16_t*)(hb + O_VT + d * VT_STRIDE + j * 2) = hs[i];
        }
        CP_WAIT(0);
    }
    __syncthreads();

    // ---- mask prefetch (pre-scaled by log2e) ----
    const float* mrow = g_mask2 + (size_t)(b & (NW - 1)) * SEQ * SEQ;
    const int m0   = warp * 16;
    const int r0   = m0 + (lane >> 2);
    const int r1   = r0 + 8;
    const int coff = (lane & 3) * 2;
    float2 mA[8], mB[8];
#pragma unroll
    for (int nt = 0; nt < 8; nt++) {
        mA[nt] = *(const float2*)&mrow[r0 * SEQ + nt * 8 + coff];
        mB[nt] = *(const float2*)&mrow[r1 * SEQ + nt * 8 + coff];
    }

    // ---- QK^T ----
    const int ar  = lane & 15;
    const int ac8 = (lane >> 4) * 8;
    const int bnp = ((lane >> 4) << 3) + (lane & 7);
    const int bc8 = ((lane >> 3) & 1) << 3;

    uint32_t ah[2][4], am[2][4];
#pragma unroll
    for (int kt = 0; kt < 2; kt++) {
        uint32_t off = (uint32_t)((m0 + ar) * QK_STRIDE + (kt * 16 + ac8) * 2);
        ldmatrix_x4(ah[kt], smem_u32(hb + O_QHI)  + off);
        ldmatrix_x4(am[kt], smem_u32(hb + O_QMID) + off);
    }

    float acc[8][4];
    uint32_t hqk[8][2];
#pragma unroll
    for (int nt = 0; nt < 8; nt++) {
#pragma unroll
        for (int e = 0; e < 4; e++) acc[nt][e] = 0.f;
        hqk[nt][0] = 0u; hqk[nt][1] = 0u;
    }

#pragma unroll
    for (int pp = 0; pp < 4; pp++) {
        uint32_t bh[2][4], bm[2][4];
#pragma unroll
        for (int kt = 0; kt < 2; kt++) {
            uint32_t off = (uint32_t)((pp * 16 + bnp) * QK_STRIDE
                                      + (kt * 16 + bc8) * 2);
            ldmatrix_x4(bh[kt], smem_u32(hb + O_KHI)  + off);
            ldmatrix_x4(bm[kt], smem_u32(hb + O_KMID) + off);
        }
#pragma unroll
        for (int kt = 0; kt < 2; kt++)
#pragma unroll
            for (int n2 = 0; n2 < 2; n2++) {
                int nt = pp * 2 + n2;
                mma_f32acc(acc[nt], ah[kt], &bh[kt][n2 * 2]);
                mma_f16acc(hqk[nt], ah[kt], &bm[kt][n2 * 2]);
                mma_f16acc(hqk[nt], am[kt], &bh[kt][n2 * 2]);
            }
    }

    // ---- softmax in log2 domain, exp in f16x2 ----
    float mx0 = -1e30f, mx1 = -1e30f;
#pragma unroll
    for (int nt = 0; nt < 8; nt++) {
        float2 cl = unpack_h2(hqk[nt][0]);
        float2 ch = unpack_h2(hqk[nt][1]);
        acc[nt][0] += cl.x + mA[nt].x;
        acc[nt][1] += cl.y + mA[nt].y;
        acc[nt][2] += ch.x + mB[nt].x;
        acc[nt][3] += ch.y + mB[nt].y;
        mx0 = fmaxf(mx0, fmaxf(acc[nt][0], acc[nt][1]));
        mx1 = fmaxf(mx1, fmaxf(acc[nt][2], acc[nt][3]));
    }
    mx0 = fmaxf(mx0, __shfl_xor_sync(0xffffffffu, mx0, 1));
    mx0 = fmaxf(mx0, __shfl_xor_sync(0xffffffffu, mx0, 2));
    mx1 = fmaxf(mx1, __shfl_xor_sync(0xffffffffu, mx1, 1));
    mx1 = fmaxf(mx1, __shfl_xor_sync(0xffffffffu, mx1, 2));

    uint32_t hp[8][2];
    float sum0 = 0.f, sum1 = 0.f;
#pragma unroll
    for (int nt = 0; nt < 8; nt++) {
        uint32_t p0 = h2ex2(pack_h2(acc[nt][0] - mx0, acc[nt][1] - mx0));
        uint32_t p1 = h2ex2(pack_h2(acc[nt][2] - mx1, acc[nt][3] - mx1));
        hp[nt][0] = p0;
        hp[nt][1] = p1;
        float2 f0 = unpack_h2(p0);
        float2 f1 = unpack_h2(p1);
        sum0 += f0.x + f0.y;
        sum1 += f1.x + f1.y;
    }
    sum0 += __shfl_xor_sync(0xffffffffu, sum0, 1);
    sum0 += __shfl_xor_sync(0xffffffffu, sum0, 2);
    sum1 += __shfl_xor_sync(0xffffffffu, sum1, 1);
    sum1 += __shfl_xor_sync(0xffffffffu, sum1, 2);

    // ---- PV (v single fp16) ----
    float oacc[4][4];
#pragma unroll
    for (int dt = 0; dt < 4; dt++)
#pragma unroll
        for (int e = 0; e < 4; e++) oacc[dt][e] = 0.f;

#pragma unroll
    for (int kt = 0; kt < 4; kt++) {
        uint32_t phf[4];
        phf[0] = hp[2 * kt][0];
        phf[1] = hp[2 * kt][1];
        phf[2] = hp[2 * kt + 1][0];
        phf[3] = hp[2 * kt + 1][1];

        uint32_t vh[2][4];
#pragma unroll
        for (int d2 = 0; d2 < 2; d2++) {
            uint32_t off = (uint32_t)((d2 * 16 + bnp) * VT_STRIDE
                                      + (kt * 16 + bc8) * 2);
            ldmatrix_x4(vh[d2], smem_u32(hb + O_VT) + off);
        }
#pragma unroll
        for (int dt = 0; dt < 4; dt++)
            mma_f32acc(oacc[dt], phf, &vh[dt >> 1][(dt & 1) * 2]);
    }

    // ---- epilogue: single fp16 out ----
    const float inv0 = 1.f / sum0;
    const float inv1 = 1.f / sum1;
#pragma unroll
    for (int dt = 0; dt < 4; dt++) {
        int col = dt * 8 + coff;
        size_t a0 = ((size_t)(b * SEQ + r0)) * CDIM + h * HDIM + col;
        size_t a1 = ((size_t)(b * SEQ + r1)) * CDIM + h * HDIM + col;
        *(uint32_t*)&g_att[a0] = pack_h2(oacc[dt][0] * inv0, oacc[dt][1] * inv0);
        *(uint32_t*)&g_att[a1] = pack_h2(oacc[dt][2] * inv1, oacc[dt][3] * inv1);
    }
}

// ---------------------------------------------------------------------------
extern "C" void kernel_launch(void* const* d_in, const int* in_sizes, int n_in,
                              void* d_out, int out_size)
{
    const float* x           = (const float*)d_in[0];
    const float* mask        = (const float*)d_in[1];
    const float* qkv_w       = (const float*)d_in[2];
    const float* qkv_b       = (const float*)d_in[3];
    const float* proj_w      = (const float*)d_in[4];
    const float* proj_b      = (const float*)d_in[5];
    const float* logit_scale = (const float*)d_in[6];
    float* out = (float*)d_out;

    __half *qkvh, *qkvm, *xh, *xm, *att, *wqh, *wqm, *wph;
    cudaGetSymbolAddress((void**)&qkvh, g_qkv_hi);
    cudaGetSymbolAddress((void**)&qkvm, g_qkv_mid);
    cudaGetSymbolAddress((void**)&xh,  g_x_hi);
    cudaGetSymbolAddress((void**)&xm,  g_x_mid);
    cudaGetSymbolAddress((void**)&att, g_att);
    cudaGetSymbolAddress((void**)&wqh, g_wq_hi);
    cudaGetSymbolAddress((void**)&wqm, g_wq_mid);
    cudaGetSymbolAddress((void**)&wph, g_wp_hi);

    cudaFuncSetAttribute(gemm_qkv_kernel,
                         cudaFuncAttributeMaxDynamicSharedMemorySize,
                         SMEM_GEMM_BYTES);
    cudaFuncSetAttribute(gemm_proj_kernel,
                         cudaFuncAttributeMaxDynamicSharedMemorySize,
                         SMEM_PROJ_BYTES);
    cudaFuncSetAttribute(attn_mma_kernel,
                         cudaFuncAttributeMaxDynamicSharedMemorySize,
                         SMEM_ATTN);

    // 0) merged init
    init_kernel<<<NB_TOTAL, 256>>>(x, mask, qkv_w, proj_w);

    // 1) QKV GEMM with fused RoPE/norm/split epilogue
    {
        dim3 grid(QKVDIM / 64, MROWS / 128);
        gemm_qkv_kernel<<<grid, 256, SMEM_GEMM_BYTES>>>(
            xh, xm, wqh, wqm, qkv_b, qkvh, qkvm, logit_scale);
    }
    // 2) Attention (2 heads per CTA)
    {
        dim3 grid(BATCH, HEADS / 2);
        attn_mma_kernel<<<grid, 256, SMEM_ATTN>>>();
    }
    // 3) Proj GEMM (pure fp16 operands, f32 accum)
    {
        dim3 grid(CDIM / 64, MROWS / 128);
        gemm_proj_kernel<<<grid, 256, SMEM_PROJ_BYTES>>>(att, wph, proj_b, out);
    }
}